// round 9
// baseline (speedup 1.0000x reference)
#include <cuda_runtime.h>
#include <cstdint>

// Accumulators in __device__ globals (no allocation allowed). Zero-initialized
// at module load; the last block resets them after finalizing so every graph
// replay starts from a clean state.
__device__ double       g_psum  = 0.0;
__device__ double       g_gsum  = 0.0;
__device__ double       g_inter = 0.0;
__device__ float        g_iou_sum = 0.0f;
__device__ unsigned int g_done = 0u;

// ---------------------------------------------------------------------------
// Single fused kernel, single-wave grid (<= 152 SMs * 8 CTAs of 256 thr).
//   blocks [0, NB)        : global sums of P, G, P*G — unroll-4 float4 stream
//   blocks [NB, NB+B*K)   : per-(b,k) region soft-IoU
//   last block to finish  : finalize scalar, write out[0], reset globals
// ---------------------------------------------------------------------------
__global__ __launch_bounds__(256) void fused_iou_kernel(
    const float* __restrict__ Pf, const float* __restrict__ Gf,
    const int* __restrict__ cents,
    long n4, int NB, int K, int H, int W, int BK,
    float* __restrict__ out)
{
    const int tid = threadIdx.x;
    const int wid = tid >> 5;
    const int lid = tid & 31;
    __shared__ float sp[8], sg[8], si[8];

    if (blockIdx.x < (unsigned)NB) {
        // ---------------- global reduction ----------------
        const float4* __restrict__ P = (const float4*)Pf;
        const float4* __restrict__ G = (const float4*)Gf;
        float ps = 0.f, gs = 0.f, is = 0.f;
        const long stride = (long)NB * blockDim.x;
        long i = (long)blockIdx.x * blockDim.x + tid;

        // Main loop: 8 independent LDG.128s in flight before any consumer.
        for (; i + 3 * stride < n4; i += 4 * stride) {
            float4 p0 = __ldcs(&P[i]);
            float4 p1 = __ldcs(&P[i + stride]);
            float4 p2 = __ldcs(&P[i + 2 * stride]);
            float4 p3 = __ldcs(&P[i + 3 * stride]);
            float4 g0 = __ldcs(&G[i]);
            float4 g1 = __ldcs(&G[i + stride]);
            float4 g2 = __ldcs(&G[i + 2 * stride]);
            float4 g3 = __ldcs(&G[i + 3 * stride]);

            ps += ((p0.x + p0.y) + (p0.z + p0.w)) + ((p1.x + p1.y) + (p1.z + p1.w))
                + ((p2.x + p2.y) + (p2.z + p2.w)) + ((p3.x + p3.y) + (p3.z + p3.w));
            gs += ((g0.x + g0.y) + (g0.z + g0.w)) + ((g1.x + g1.y) + (g1.z + g1.w))
                + ((g2.x + g2.y) + (g2.z + g2.w)) + ((g3.x + g3.y) + (g3.z + g3.w));
            is += (p0.x * g0.x + p0.y * g0.y + p0.z * g0.z + p0.w * g0.w)
                + (p1.x * g1.x + p1.y * g1.y + p1.z * g1.z + p1.w * g1.w)
                + (p2.x * g2.x + p2.y * g2.y + p2.z * g2.z + p2.w * g2.w)
                + (p3.x * g3.x + p3.y * g3.y + p3.z * g3.z + p3.w * g3.w);
        }
        // Remainder (empty for the 32 MiB shape, but keep it general).
        for (; i < n4; i += stride) {
            float4 p = __ldcs(&P[i]);
            float4 g = __ldcs(&G[i]);
            ps += (p.x + p.y) + (p.z + p.w);
            gs += (g.x + g.y) + (g.z + g.w);
            is += p.x * g.x + p.y * g.y + p.z * g.z + p.w * g.w;
        }

        #pragma unroll
        for (int o = 16; o > 0; o >>= 1) {
            ps += __shfl_down_sync(0xffffffffu, ps, o);
            gs += __shfl_down_sync(0xffffffffu, gs, o);
            is += __shfl_down_sync(0xffffffffu, is, o);
        }
        if (lid == 0) { sp[wid] = ps; sg[wid] = gs; si[wid] = is; }
        __syncthreads();
        if (wid == 0) {
            int nw = blockDim.x >> 5;
            ps = (lid < nw) ? sp[lid] : 0.f;
            gs = (lid < nw) ? sg[lid] : 0.f;
            is = (lid < nw) ? si[lid] : 0.f;
            #pragma unroll
            for (int o = 4; o > 0; o >>= 1) {
                ps += __shfl_down_sync(0xffffffffu, ps, o);
                gs += __shfl_down_sync(0xffffffffu, gs, o);
                is += __shfl_down_sync(0xffffffffu, is, o);
            }
            if (lid == 0) {
                atomicAdd(&g_psum,  (double)ps);
                atomicAdd(&g_gsum,  (double)gs);
                atomicAdd(&g_inter, (double)is);
            }
        }
    } else {
        // ---------------- region IoU for one (b, k) ----------------
        int r = blockIdx.x - NB;
        int b = r / K;
        int k = r % K;
        int cy = cents[(b * K + k) * 2 + 0];
        int cx = cents[(b * K + k) * 2 + 1];

        // Replicates _bounds exactly (parity fix uses the UPDATED end).
        int sy = max(cy - 20, 0), ey = min(cy + 20, H);
        {
            int ny = ey - sy;
            bool odd = ((ny & 1) != 0) && (ny < 40);
            if (odd && sy == 0) ey -= 1;
            if (odd && ey == H) sy += 1;
        }
        int sx = max(cx - 20, 0), ex = min(cx + 20, W);
        {
            int nx = ex - sx;
            bool odd = ((nx & 1) != 0) && (nx < 40);
            if (odd && sx == 0) ex -= 1;
            if (odd && ex == W) sx += 1;
        }

        int wy = ey - sy, wx = ex - sx;
        int cnt = wy * wx;
        const float* Pb = Pf + (size_t)b * H * W;
        const float* Gb = Gf + (size_t)b * H * W;

        float ps = 0.f, gs = 0.f, is = 0.f;
        for (int i2 = tid; i2 < cnt; i2 += blockDim.x) {
            int yy = sy + i2 / wx;
            int xx = sx + i2 % wx;
            size_t off = (size_t)yy * W + xx;
            float p = Pb[off];
            float g = Gb[off];
            ps += p; gs += g; is += p * g;
        }
        #pragma unroll
        for (int o = 16; o > 0; o >>= 1) {
            ps += __shfl_down_sync(0xffffffffu, ps, o);
            gs += __shfl_down_sync(0xffffffffu, gs, o);
            is += __shfl_down_sync(0xffffffffu, is, o);
        }
        if (lid == 0) { sp[wid] = ps; sg[wid] = gs; si[wid] = is; }
        __syncthreads();
        if (tid == 0) {
            int nw = blockDim.x >> 5;
            float tp = 0.f, tg = 0.f, ti = 0.f;
            for (int w = 0; w < nw; w++) { tp += sp[w]; tg += sg[w]; ti += si[w]; }
            float iou = (ti + 1.0f) / (tp + tg - ti + 1.0f);
            atomicAdd(&g_iou_sum, iou);
        }
    }

    // ---------------- last-block finalize + reset ----------------
    __syncthreads();
    if (tid == 0) {
        __threadfence();
        unsigned int total = (unsigned)NB + (unsigned)BK;
        unsigned int prev = atomicAdd(&g_done, 1u);
        if (prev == total - 1u) {
            double inter = atomicAdd(&g_inter, 0.0);
            double psum  = atomicAdd(&g_psum, 0.0);
            double gsum  = atomicAdd(&g_gsum, 0.0);
            float  iou   = atomicAdd(&g_iou_sum, 0.0f);
            double loss_global = 1.0 - (inter + 1.0) / (psum + gsum - inter + 1.0);
            double loss_region = 1.0 - (double)iou / (double)BK;
            out[0] = (float)(loss_global + loss_region);
            g_psum = 0.0; g_gsum = 0.0; g_inter = 0.0;
            g_iou_sum = 0.0f;
            __threadfence();
            g_done = 0u;
        }
    }
}

extern "C" void kernel_launch(void* const* d_in, const int* in_sizes, int n_in,
                              void* d_out, int out_size)
{
    const float* preds = (const float*)d_in[0];
    const float* gt    = (const float*)d_in[1];
    const int*   cents = (const int*)d_in[2];
    float* out = (float*)d_out;

    const int H = 1024, W = 1024;
    long n  = (long)in_sizes[0];
    int  B  = (int)(n / ((long)H * W));
    int  K  = in_sizes[2] / (2 * B);
    int  BK = B * K;
    long n4 = n / 4;

    // Single wave: 1024 reduce blocks + BK region blocks <= 152 SMs * 8 CTAs.
    const int NB = 1024;
    fused_iou_kernel<<<NB + BK, 256>>>(preds, gt, cents, n4, NB, K, H, W, BK, out);
}